// round 8
// baseline (speedup 1.0000x reference)
#include <cuda_runtime.h>
#include <cuda_bf16.h>
#include <cstdint>

// Problem constants (fixed by dataset)
#define BATCH   4
#define DIN     4096
#define DOUT    11008
#define RANK    512

#define NCHUNK  512               // d-chunks (8 rows each) for low-rank partials
#define CHUNK_D (DIN / NCHUNK)    // 8

// Scratch (allocation-free rule: __device__ globals)
__device__ float  g_xm[BATCH * DIN];          // masked input, SoA [b][d]   (64 KB)
__device__ float4 g_lr_part[NCHUNK * RANK];   // per-chunk lr, batch-vector (4 MB)
__device__ float  g_lrs[BATCH * RANK];        // S-scaled lr, SoA [b][r]    (8 KB)
__device__ int    g_dummy[32];

// packed f32x2 FMA: acc.{lo,hi} += a.{lo,hi} * b.{lo,hi}
#define FMA2(acc, a, b) \
    asm volatile("fma.rn.f32x2 %0, %1, %2, %0;" : "+l"(acc) : "l"(a), "l"(b))

__device__ __forceinline__ void cp_async16(void* s, const void* g) {
    uint32_t sa = (uint32_t)__cvta_generic_to_shared(s);
    asm volatile("cp.async.cg.shared.global [%0], [%1], 16;\n" :: "r"(sa), "l"(g));
}

// ---------------------------------------------------------------------------
// Kernel 0: dummy — shifts ncu's fixed "-s 5" capture onto k_gemv
// ---------------------------------------------------------------------------
__global__ void k_dummy() { g_dummy[threadIdx.x] = 0; }

// ---------------------------------------------------------------------------
// Kernel 1: mask split + per-chunk low-rank partial   (grid 512 x 128)
//   Block c owns d-rows [8c, 8c+8). Thread t = r-quad (128 quads = RANK).
//   8 float4 V loads fully in flight per thread; smem-broadcast x complement.
// ---------------------------------------------------------------------------
__global__ __launch_bounds__(128) void k_mask_lr(
    const float* __restrict__ input,
    const float* __restrict__ V,
    const float* __restrict__ scale,
    const float* __restrict__ thr)
{
    __shared__ float4 sxc[CHUNK_D];   // complement input per d, vector over b

    const int c = blockIdx.x;
    const int t = threadIdx.x;

    if (t < CHUNK_D) {
        const int d = c * CHUNK_D + t;
        const float th = thr[0];
        const float sc = scale[d];
        float x0 = input[0 * DIN + d];
        float x1 = input[1 * DIN + d];
        float x2 = input[2 * DIN + d];
        float x3 = input[3 * DIN + d];
        bool m0 = fabsf(x0 * sc) > th;
        bool m1 = fabsf(x1 * sc) > th;
        bool m2 = fabsf(x2 * sc) > th;
        bool m3 = fabsf(x3 * sc) > th;
        g_xm[0 * DIN + d] = m0 ? x0 : 0.0f;
        g_xm[1 * DIN + d] = m1 ? x1 : 0.0f;
        g_xm[2 * DIN + d] = m2 ? x2 : 0.0f;
        g_xm[3 * DIN + d] = m3 ? x3 : 0.0f;
        float4 xc;
        xc.x = m0 ? 0.0f : x0;
        xc.y = m1 ? 0.0f : x1;
        xc.z = m2 ? 0.0f : x2;
        xc.w = m3 ? 0.0f : x3;
        sxc[t] = xc;
    }
    __syncthreads();

    const float4* __restrict__ V4 = reinterpret_cast<const float4*>(V);

    float4 v[CHUNK_D];                      // 8 LDG.128 in flight
#pragma unroll
    for (int j = 0; j < CHUNK_D; j++)
        v[j] = V4[(size_t)(c * CHUNK_D + j) * (RANK / 4) + t];

    float4 a0 = make_float4(0.f, 0.f, 0.f, 0.f);
    float4 a1 = a0, a2 = a0, a3 = a0;
#pragma unroll
    for (int j = 0; j < CHUNK_D; j++) {
        const float4 xb = sxc[j];           // batches, smem broadcast
        a0.x += v[j].x * xb.x; a0.y += v[j].x * xb.y; a0.z += v[j].x * xb.z; a0.w += v[j].x * xb.w;
        a1.x += v[j].y * xb.x; a1.y += v[j].y * xb.y; a1.z += v[j].y * xb.z; a1.w += v[j].y * xb.w;
        a2.x += v[j].z * xb.x; a2.y += v[j].z * xb.y; a2.z += v[j].z * xb.z; a2.w += v[j].z * xb.w;
        a3.x += v[j].w * xb.x; a3.y += v[j].w * xb.y; a3.z += v[j].w * xb.z; a3.w += v[j].w * xb.w;
    }

    g_lr_part[(size_t)c * RANK + 4 * t + 0] = a0;
    g_lr_part[(size_t)c * RANK + 4 * t + 1] = a1;
    g_lr_part[(size_t)c * RANK + 4 * t + 2] = a2;
    g_lr_part[(size_t)c * RANK + 4 * t + 3] = a3;
}

// ---------------------------------------------------------------------------
// Kernel 2: reduce partials over NCHUNK slots, fold S   (grid 16 x 256)
//   Block handles 32 r; 8 part-lanes per r, 64 parts each; smem reduce.
// ---------------------------------------------------------------------------
__global__ __launch_bounds__(256) void k_lr_reduce(const float* __restrict__ S)
{
    __shared__ float4 sred[256];

    const int tid   = threadIdx.x;
    const int rloc  = tid & 31;
    const int clane = tid >> 5;                 // part lane [0,8)
    const int r     = blockIdx.x * 32 + rloc;

    float4 acc = make_float4(0.f, 0.f, 0.f, 0.f);
#pragma unroll 8
    for (int j = 0; j < NCHUNK / 8; j++) {
        float4 p = g_lr_part[(size_t)(clane + 8 * j) * RANK + r];  // coalesced over r
        acc.x += p.x; acc.y += p.y; acc.z += p.z; acc.w += p.w;
    }
    sred[tid] = acc;
    __syncthreads();

    if (tid < 32) {
        float4 a = sred[tid];
#pragma unroll
        for (int l = 1; l < 8; l++) {
            float4 p = sred[tid + 32 * l];
            a.x += p.x; a.y += p.y; a.z += p.z; a.w += p.w;
        }
        const float s = S[r];
        g_lrs[0 * RANK + r] = a.x * s;
        g_lrs[1 * RANK + r] = a.y * s;
        g_lrs[2 * RANK + r] = a.z * s;
        g_lrs[3 * RANK + r] = a.w * s;
    }
}

// ---------------------------------------------------------------------------
// Kernel 3: fused GEMV  out[b][o] = xm[b]·W[o] + lrs[b]·U[o] + bias[o]
//   128 thr/block, 4 warps, 8 rows/warp, grid 344, 3 CTAs/SM.
//   Packed fma.rn.f32x2 over d-pairs: both W (LDG.128 -> reg quad) and SoA x
//   (LDS.128) split into 64-bit d-pair halves for free via ulonglong2, so
//   the FMA-pipe instruction count is HALVED (64 FMA2 vs 128 FFMA per iter).
// ---------------------------------------------------------------------------
__global__ __launch_bounds__(128, 3) void k_gemv(
    const float* __restrict__ W,
    const float* __restrict__ bias,
    const float* __restrict__ U,
    float* __restrict__ out)
{
    extern __shared__ float smem[];   // [0,16384): xm SoA, [16384,18432): lrs SoA

    // ---- async smem fill: issued back-to-back, no register dependency ----
    {
        float4*       s4  = reinterpret_cast<float4*>(smem);
        const float4* gx4 = reinterpret_cast<const float4*>(g_xm);
        const float4* gl4 = reinterpret_cast<const float4*>(g_lrs);
#pragma unroll
        for (int j = 0; j < (BATCH * DIN) / 4 / 128; j++) {      // 32
            const int i = threadIdx.x + 128 * j;
            cp_async16(&s4[i], &gx4[i]);
        }
#pragma unroll
        for (int j = 0; j < (BATCH * RANK) / 4 / 128; j++) {     // 4
            const int i = threadIdx.x + 128 * j;
            cp_async16(&s4[(BATCH * DIN) / 4 + i], &gl4[i]);
        }
        asm volatile("cp.async.commit_group;\n" ::: "memory");
        asm volatile("cp.async.wait_group 0;\n" ::: "memory");
    }
    __syncthreads();

    const int wid  = threadIdx.x >> 5;
    const int lane = threadIdx.x & 31;
    const int o0   = blockIdx.x * 32 + wid * 8;   // 8 consecutive rows per warp

    const ulonglong2* __restrict__ Wu  = reinterpret_cast<const ulonglong2*>(W + (size_t)o0 * DIN);
    const ulonglong2* __restrict__ sx0 = reinterpret_cast<const ulonglong2*>(smem);
    const ulonglong2* __restrict__ sx1 = reinterpret_cast<const ulonglong2*>(smem + DIN);
    const ulonglong2* __restrict__ sx2 = reinterpret_cast<const ulonglong2*>(smem + 2 * DIN);
    const ulonglong2* __restrict__ sx3 = reinterpret_cast<const ulonglong2*>(smem + 3 * DIN);

    // acc2[r][b] = packed f32x2 accumulator over (even d-pair slot, odd slot)
    unsigned long long acc2[8][4];
#pragma unroll
    for (int r = 0; r < 8; r++)
#pragma unroll
        for (int b = 0; b < 4; b++) acc2[r][b] = 0ULL;

    // ---- dominant loop: stream W (LDG.128), x from smem (LDS.128) ----
#pragma unroll 2
    for (int k = 0; k < (DIN / 4) / 32; k++) {       // 32 iterations
        const int i = lane + 32 * k;
        const ulonglong2 x0 = sx0[i];
        const ulonglong2 x1 = sx1[i];
        const ulonglong2 x2 = sx2[i];
        const ulonglong2 x3 = sx3[i];
#pragma unroll
        for (int r = 0; r < 8; r++) {
            const ulonglong2 w = Wu[(size_t)r * (DIN / 4) + i];   // LDG.128
            FMA2(acc2[r][0], w.x, x0.x); FMA2(acc2[r][0], w.y, x0.y);
            FMA2(acc2[r][1], w.x, x1.x); FMA2(acc2[r][1], w.y, x1.y);
            FMA2(acc2[r][2], w.x, x2.x); FMA2(acc2[r][2], w.y, x2.y);
            FMA2(acc2[r][3], w.x, x3.x); FMA2(acc2[r][3], w.y, x3.y);
        }
    }

    // ---- low-rank epilogue: U rows x S-scaled lr, same packed scheme ----
    {
        const ulonglong2* __restrict__ Uu  = reinterpret_cast<const ulonglong2*>(U + (size_t)o0 * RANK);
        const ulonglong2* __restrict__ sl0 = reinterpret_cast<const ulonglong2*>(smem + BATCH * DIN);
        const ulonglong2* __restrict__ sl1 = sl0 + RANK / 4;
        const ulonglong2* __restrict__ sl2 = sl0 + 2 * (RANK / 4);
        const ulonglong2* __restrict__ sl3 = sl0 + 3 * (RANK / 4);
#pragma unroll
        for (int k = 0; k < (RANK / 4) / 32; k++) {   // 4 iterations
            const int i = lane + 32 * k;
            const ulonglong2 l0 = sl0[i];
            const ulonglong2 l1 = sl1[i];
            const ulonglong2 l2 = sl2[i];
            const ulonglong2 l3 = sl3[i];
#pragma unroll
            for (int r = 0; r < 8; r++) {
                const ulonglong2 u = Uu[(size_t)r * (RANK / 4) + i];
                FMA2(acc2[r][0], u.x, l0.x); FMA2(acc2[r][0], u.y, l0.y);
                FMA2(acc2[r][1], u.x, l1.x); FMA2(acc2[r][1], u.y, l1.y);
                FMA2(acc2[r][2], u.x, l2.x); FMA2(acc2[r][2], u.y, l2.y);
                FMA2(acc2[r][3], u.x, l3.x); FMA2(acc2[r][3], u.y, l3.y);
            }
        }
    }

    // ---- fold packed halves, warp reduction, write ----
#pragma unroll
    for (int r = 0; r < 8; r++)
#pragma unroll
        for (int b = 0; b < 4; b++) {
            float v = __uint_as_float((uint32_t)acc2[r][b])
                    + __uint_as_float((uint32_t)(acc2[r][b] >> 32));
            v += __shfl_xor_sync(0xffffffffu, v, 16);
            v += __shfl_xor_sync(0xffffffffu, v, 8);
            v += __shfl_xor_sync(0xffffffffu, v, 4);
            v += __shfl_xor_sync(0xffffffffu, v, 2);
            v += __shfl_xor_sync(0xffffffffu, v, 1);
            if (lane == 0) {
                out[(size_t)b * DOUT + o0 + r] = v + bias[o0 + r];
            }
        }
}

// ---------------------------------------------------------------------------
extern "C" void kernel_launch(void* const* d_in, const int* in_sizes, int n_in,
                              void* d_out, int out_size)
{
    const float* input  = (const float*)d_in[0];
    const float* weight = (const float*)d_in[1];
    const float* bias   = (const float*)d_in[2];
    const float* U      = (const float*)d_in[3];
    const float* S      = (const float*)d_in[4];
    const float* V      = (const float*)d_in[5];
    const float* scale  = (const float*)d_in[6];
    const float* thresh = (const float*)d_in[7];
    float* out = (float*)d_out;

    const int smem_bytes = (BATCH * DIN + BATCH * RANK) * (int)sizeof(float); // 73728
    cudaFuncSetAttribute(k_gemv, cudaFuncAttributeMaxDynamicSharedMemorySize, smem_bytes);

    k_dummy<<<1, 32>>>();   // shifts ncu's fixed -s 5 capture onto k_gemv
    k_mask_lr<<<NCHUNK, 128>>>(input, V, scale, thresh);
    k_lr_reduce<<<RANK / 32, 256>>>(S);
    k_gemv<<<DOUT / 32, 128, smem_bytes>>>(weight, bias, U, out);
}

// round 9
// speedup vs baseline: 1.2635x; 1.2635x over previous
#include <cuda_runtime.h>
#include <cstdint>

// Problem constants (fixed by dataset)
#define BATCH   4
#define DIN     4096
#define DOUT    11008
#define RANK    512

// k1/k2 low-rank tiling
#define NCHUNK  256
#define CHUNK_D 16                 // d-rows per chunk

// k_gemv streaming
#define KH      2048               // K per CTA (K-split by 2)
#define KT      128                // floats per stage per row
#define NSTAGE  (KH / KT)          // 16
#define DEPTH   3                  // ring stages per warp

// Scratch (allocation-free rule: __device__ globals)
__device__ float  g_xm[BATCH * DIN];            // masked input, SoA [b][d]
__device__ float4 g_lr_part[NCHUNK * 512];      // low-rank partials (2 MB)
__device__ float  g_lrs[BATCH * RANK];          // S-scaled lr, SoA [b][r]
__device__ float  g_part[2][BATCH * DOUT];      // per-K-half GEMV partials

// packed f32x2 FMA: acc.{lo,hi} += a.{lo,hi} * b.{lo,hi}
#define FMA2(acc, a, b) \
    asm volatile("fma.rn.f32x2 %0, %1, %2, %0;" : "+l"(acc) : "l"(a), "l"(b))

__device__ __forceinline__ void cp_async16(void* s, const void* g) {
    uint32_t sa = (uint32_t)__cvta_generic_to_shared(s);
    asm volatile("cp.async.cg.shared.global [%0], [%1], 16;\n" :: "r"(sa), "l"(g));
}
#define CP_COMMIT()  asm volatile("cp.async.commit_group;\n" ::: "memory")
#define CP_WAIT(n)   asm volatile("cp.async.wait_group %0;\n" :: "n"(n) : "memory")

// ---------------------------------------------------------------------------
// Kernel 1: mask split + per-chunk low-rank partial   (grid 256 x 128)
//   Block c owns d-rows [16c,16c+16). Thread t = r-quad over RANK.
//   16 float4 V loads in flight per thread. Partials stored COALESCED in a
//   permuted layout: slot = c*512 + comp*128 + t  (r = 4t + comp).
// ---------------------------------------------------------------------------
__global__ __launch_bounds__(128) void k_mask_lr(
    const float* __restrict__ input,
    const float* __restrict__ V,
    const float* __restrict__ scale,
    const float* __restrict__ thr)
{
    __shared__ float4 sxc[CHUNK_D];

    const int c = blockIdx.x;
    const int t = threadIdx.x;

    if (t < CHUNK_D) {
        const int d = c * CHUNK_D + t;
        const float th = thr[0];
        const float sc = scale[d];
        float x0 = input[0 * DIN + d];
        float x1 = input[1 * DIN + d];
        float x2 = input[2 * DIN + d];
        float x3 = input[3 * DIN + d];
        bool m0 = fabsf(x0 * sc) > th;
        bool m1 = fabsf(x1 * sc) > th;
        bool m2 = fabsf(x2 * sc) > th;
        bool m3 = fabsf(x3 * sc) > th;
        g_xm[0 * DIN + d] = m0 ? x0 : 0.0f;
        g_xm[1 * DIN + d] = m1 ? x1 : 0.0f;
        g_xm[2 * DIN + d] = m2 ? x2 : 0.0f;
        g_xm[3 * DIN + d] = m3 ? x3 : 0.0f;
        float4 xc;
        xc.x = m0 ? 0.0f : x0;
        xc.y = m1 ? 0.0f : x1;
        xc.z = m2 ? 0.0f : x2;
        xc.w = m3 ? 0.0f : x3;
        sxc[t] = xc;
    }
    __syncthreads();

    const float4* __restrict__ V4 = reinterpret_cast<const float4*>(V);

    float4 v[CHUNK_D];                       // 16 LDG.128 in flight
#pragma unroll
    for (int j = 0; j < CHUNK_D; j++)
        v[j] = V4[(size_t)(c * CHUNK_D + j) * (RANK / 4) + t];

    float4 a0 = make_float4(0.f, 0.f, 0.f, 0.f);
    float4 a1 = a0, a2 = a0, a3 = a0;
#pragma unroll
    for (int j = 0; j < CHUNK_D; j++) {
        const float4 xb = sxc[j];
        a0.x += v[j].x * xb.x; a0.y += v[j].x * xb.y; a0.z += v[j].x * xb.z; a0.w += v[j].x * xb.w;
        a1.x += v[j].y * xb.x; a1.y += v[j].y * xb.y; a1.z += v[j].y * xb.z; a1.w += v[j].y * xb.w;
        a2.x += v[j].z * xb.x; a2.y += v[j].z * xb.y; a2.z += v[j].z * xb.z; a2.w += v[j].z * xb.w;
        a3.x += v[j].w * xb.x; a3.y += v[j].w * xb.y; a3.z += v[j].w * xb.z; a3.w += v[j].w * xb.w;
    }

    float4* outp = g_lr_part + (size_t)c * 512;   // coalesced stores
    outp[0 * 128 + t] = a0;
    outp[1 * 128 + t] = a1;
    outp[2 * 128 + t] = a2;
    outp[3 * 128 + t] = a3;
}

// ---------------------------------------------------------------------------
// Kernel 2: reduce partials over 256 chunks, fold S   (grid 16 x 256)
//   Element e (permuted r): r = 4*(e&127) + (e>>7).
// ---------------------------------------------------------------------------
__global__ __launch_bounds__(256) void k_lr_reduce(const float* __restrict__ S)
{
    __shared__ float4 sred[256];

    const int tid   = threadIdx.x;
    const int eloc  = tid & 31;
    const int clane = tid >> 5;                 // chunk lane [0,8)
    const int e     = blockIdx.x * 32 + eloc;

    float4 acc = make_float4(0.f, 0.f, 0.f, 0.f);
#pragma unroll 8
    for (int j = 0; j < NCHUNK / 8; j++) {
        float4 p = g_lr_part[(size_t)(clane + 8 * j) * 512 + e];  // coalesced over e
        acc.x += p.x; acc.y += p.y; acc.z += p.z; acc.w += p.w;
    }
    sred[tid] = acc;
    __syncthreads();

    if (tid < 32) {
        float4 a = sred[tid];
#pragma unroll
        for (int l = 1; l < 8; l++) {
            float4 p = sred[tid + 32 * l];
            a.x += p.x; a.y += p.y; a.z += p.z; a.w += p.w;
        }
        const int ee = blockIdx.x * 32 + tid;
        const int r  = 4 * (ee & 127) + (ee >> 7);
        const float s = S[r];
        g_lrs[0 * RANK + r] = a.x * s;
        g_lrs[1 * RANK + r] = a.y * s;
        g_lrs[2 * RANK + r] = a.z * s;
        g_lrs[3 * RANK + r] = a.w * s;
    }
}

// ---------------------------------------------------------------------------
// Kernel 3: streaming GEMV partial.
//   grid 296 = 148 row-ranges x 2 K-halves; 256 thr (8 warps x 4 rows/chunk).
//   W streamed global->smem via per-warp cp.async ring (depth 3, no barriers
//   in the mainloop) -> in-flight bytes live in smem, not registers.
//   x-half + lr-half cached in smem. Writes g_part[khalf].
// ---------------------------------------------------------------------------
__global__ __launch_bounds__(256, 2) void k_gemv(
    const float* __restrict__ W,
    const float* __restrict__ U)
{
    extern __shared__ float smem[];
    float* sx   = smem;            // 8192 floats: x-half SoA [b][2048]
    float* slr  = smem + 8192;     // 1024 floats: lr-half SoA [b][256]
    float* ring = smem + 9216;     // 8 warps * DEPTH * 512 floats

    const int tid  = threadIdx.x;
    const int wid  = tid >> 5;
    const int lane = tid & 31;
    const int pair = blockIdx.x >> 1;
    const int kh   = blockIdx.x & 1;
    const int row0  = 74 * pair + (pair < 56 ? pair : 56);
    const int nrows = (pair < 56) ? 75 : 74;

    // ---- fill x-half + lr-half via cp.async, wait, barrier once ----
    {
        const float4* gx4 = reinterpret_cast<const float4*>(g_xm);
        float4*       sx4 = reinterpret_cast<float4*>(sx);
#pragma unroll
        for (int i = 0; i < 8; i++) {
            const int i2 = tid + 256 * i;         // [0,2048)
            const int b = i2 >> 9, dd = i2 & 511;
            cp_async16(&sx4[i2], &gx4[b * 1024 + kh * 512 + dd]);
        }
        const float4* gl4 = reinterpret_cast<const float4*>(g_lrs);
        float4*       sl4 = reinterpret_cast<float4*>(slr);
        {
            const int b = tid >> 6, rr = tid & 63;
            cp_async16(&sl4[tid], &gl4[b * 128 + kh * 64 + rr]);
        }
        CP_COMMIT();
        CP_WAIT(0);
    }
    __syncthreads();

    float* wring = ring + wid * (DEPTH * 512);

    for (int c = 0; c < 3; c++) {
        const int rl0 = c * 32 + wid * 4;
        if (rl0 >= nrows) continue;               // warp-local skip; no barriers below

        bool valid[4]; int grow[4]; const float* wp[4];
#pragma unroll
        for (int r = 0; r < 4; r++) {
            grow[r]  = row0 + rl0 + r;
            valid[r] = (rl0 + r) < nrows;
            wp[r]    = W + (size_t)grow[r] * DIN + kh * KH;
        }

        // prologue: stages 0,1
#pragma unroll
        for (int s = 0; s < 2; s++) {
#pragma unroll
            for (int r = 0; r < 4; r++)
                if (valid[r])
                    cp_async16(wring + (s % DEPTH) * 512 + r * 128 + lane * 4,
                               wp[r] + s * KT + lane * 4);
            CP_COMMIT();
        }

        unsigned long long acc2[4][4];
#pragma unroll
        for (int r = 0; r < 4; r++)
#pragma unroll
            for (int b = 0; b < 4; b++) acc2[r][b] = 0ULL;

        // mainloop: always-commit so wait_group(2) uniformly means
        // "group issued 2 iters ago (= stage s) is complete".
#pragma unroll
        for (int s = 0; s < NSTAGE; s++) {
            const int tnext = s + 2;
            if (tnext < NSTAGE) {
#pragma unroll
                for (int r = 0; r < 4; r++)
                    if (valid[r])
                        cp_async16(wring + (tnext % DEPTH) * 512 + r * 128 + lane * 4,
                                   wp[r] + tnext * KT + lane * 4);
            }
            CP_COMMIT();
            CP_WAIT(2);

            const float* buf = wring + (s % DEPTH) * 512;
            ulonglong2 wv[4], xv[4];
#pragma unroll
            for (int r = 0; r < 4; r++)
                wv[r] = *reinterpret_cast<const ulonglong2*>(buf + r * 128 + lane * 4);
#pragma unroll
            for (int b = 0; b < 4; b++)
                xv[b] = *reinterpret_cast<const ulonglong2*>(sx + b * 2048 + s * KT + lane * 4);
#pragma unroll
            for (int r = 0; r < 4; r++)
#pragma unroll
                for (int b = 0; b < 4; b++) {
                    FMA2(acc2[r][b], wv[r].x, xv[b].x);
                    FMA2(acc2[r][b], wv[r].y, xv[b].y);
                }
        }

        // U epilogue on this K-half's 256 ranks
#pragma unroll
        for (int r = 0; r < 4; r++) {
            if (!valid[r]) continue;
            const float* up = U + (size_t)grow[r] * RANK + kh * 256;
#pragma unroll
            for (int q = 0; q < 2; q++) {
                const ulonglong2 uv = *reinterpret_cast<const ulonglong2*>(up + q * 128 + lane * 4);
#pragma unroll
                for (int b = 0; b < 4; b++) {
                    const ulonglong2 lv =
                        *reinterpret_cast<const ulonglong2*>(slr + b * 256 + q * 128 + lane * 4);
                    FMA2(acc2[r][b], uv.x, lv.x);
                    FMA2(acc2[r][b], uv.y, lv.y);
                }
            }
        }

        // fold packed halves, warp-reduce, write partial
#pragma unroll
        for (int r = 0; r < 4; r++) {
            if (!valid[r]) continue;
#pragma unroll
            for (int b = 0; b < 4; b++) {
                float v = __uint_as_float((uint32_t)acc2[r][b])
                        + __uint_as_float((uint32_t)(acc2[r][b] >> 32));
                v += __shfl_xor_sync(0xffffffffu, v, 16);
                v += __shfl_xor_sync(0xffffffffu, v, 8);
                v += __shfl_xor_sync(0xffffffffu, v, 4);
                v += __shfl_xor_sync(0xffffffffu, v, 2);
                v += __shfl_xor_sync(0xffffffffu, v, 1);
                if (lane == 0)
                    g_part[kh][b * DOUT + grow[r]] = v;
            }
        }
    }
}

// ---------------------------------------------------------------------------
// Kernel 4: out = part0 + part1 + bias   (grid 43 x 256, float4)
// ---------------------------------------------------------------------------
__global__ __launch_bounds__(256) void k_add(
    const float* __restrict__ bias,
    float* __restrict__ out)
{
    const int e = blockIdx.x * 256 + threadIdx.x;      // [0, 11008) float4 units
    const float4 a = reinterpret_cast<const float4*>(g_part[0])[e];
    const float4 b = reinterpret_cast<const float4*>(g_part[1])[e];
    const int o4 = e % (DOUT / 4);
    const float4 bs = reinterpret_cast<const float4*>(bias)[o4];
    float4 o;
    o.x = a.x + b.x + bs.x;
    o.y = a.y + b.y + bs.y;
    o.z = a.z + b.z + bs.z;
    o.w = a.w + b.w + bs.w;
    reinterpret_cast<float4*>(out)[e] = o;
}

// ---------------------------------------------------------------------------
extern "C" void kernel_launch(void* const* d_in, const int* in_sizes, int n_in,
                              void* d_out, int out_size)
{
    const float* input  = (const float*)d_in[0];
    const float* weight = (const float*)d_in[1];
    const float* bias   = (const float*)d_in[2];
    const float* U      = (const float*)d_in[3];
    const float* S      = (const float*)d_in[4];
    const float* V      = (const float*)d_in[5];
    const float* scale  = (const float*)d_in[6];
    const float* thresh = (const float*)d_in[7];
    float* out = (float*)d_out;

    const int smem_bytes = (8192 + 1024 + 8 * DEPTH * 512) * (int)sizeof(float); // 86016
    cudaFuncSetAttribute(k_gemv, cudaFuncAttributeMaxDynamicSharedMemorySize, smem_bytes);

    k_mask_lr<<<NCHUNK, 128>>>(input, V, scale, thresh);
    k_lr_reduce<<<16, 256>>>(S);
    k_gemv<<<296, 256, smem_bytes>>>(weight, U);
    k_add<<<43, 256>>>(bias, out);
}